// round 1
// baseline (speedup 1.0000x reference)
#include <cuda_runtime.h>

// ChebConv K=4: N=50000 nodes, E=800000 edges, 64 in-feats, 256 out-feats.
// Plan: build CSR-by-dst (count + scan + fill), then 3 gather-sum Laplacian
// applies (atomic-free, L2-resident), recurrence fused with y=X*ds precompute,
// then fp32 128x128 register-blocked SGEMM with bias+ReLU epilogue.

#define NMAX 50000
#define EMAX 800000
#define NF   64          // input feats
#define NFK  256         // concat feats (64*4)

// ---------------- scratch (static device globals; no allocation) -----------
__device__ int   g_deg[NMAX];
__device__ int   g_rowptr[NMAX + 1];
__device__ int   g_cursor[NMAX];
__device__ int   g_blocksum[64];
__device__ int   g_srcs[EMAX];
__device__ float g_ds[NMAX];
__device__ float g_y[NMAX * NF];      // X_prev * d^{-1/2}
__device__ float g_agg[NMAX * NF];    // scatter result (pre-ds scaling)
__device__ float g_Xcat[(size_t)NMAX * NFK];  // [N, 256] concat of X0..X3

// ---------------- CSR build ------------------------------------------------
__global__ void zero_deg_kernel(int n) {
    int i = blockIdx.x * blockDim.x + threadIdx.x;
    if (i < n) g_deg[i] = 0;
}

__global__ void count_deg_kernel(const int* __restrict__ dst, int e) {
    int i = blockIdx.x * blockDim.x + threadIdx.x;
    if (i < e) atomicAdd(&g_deg[dst[i]], 1);
}

// Block-wise inclusive scan of g_deg into g_rowptr[i+1]; block sums out.
__global__ void scanA_kernel(int n) {
    __shared__ int sh[1024];
    int i = blockIdx.x * 1024 + threadIdx.x;
    int v = (i < n) ? g_deg[i] : 0;
    sh[threadIdx.x] = v;
    __syncthreads();
    for (int off = 1; off < 1024; off <<= 1) {
        int u = (threadIdx.x >= (unsigned)off) ? sh[threadIdx.x - off] : 0;
        __syncthreads();
        sh[threadIdx.x] += u;
        __syncthreads();
    }
    if (i < n) g_rowptr[i + 1] = sh[threadIdx.x];
    if (threadIdx.x == 1023) g_blocksum[blockIdx.x] = sh[1023];
}

// Exclusive scan of block sums (nb <= 64), single block of 64 threads.
__global__ void scanB_kernel(int nb) {
    __shared__ int sh[64];
    int t = threadIdx.x;
    int v = (t < nb) ? g_blocksum[t] : 0;
    sh[t] = v;
    __syncthreads();
    for (int off = 1; off < 64; off <<= 1) {
        int u = (t >= off) ? sh[t - off] : 0;
        __syncthreads();
        sh[t] += u;
        __syncthreads();
    }
    if (t < nb) g_blocksum[t] = sh[t] - v;  // exclusive
}

__global__ void scanC_kernel(int n) {
    int i = blockIdx.x * 1024 + threadIdx.x;
    if (i < n) g_rowptr[i + 1] += g_blocksum[blockIdx.x];
    if (i == 0) g_rowptr[0] = 0;
}

// cursor = rowptr (start of each segment); ds = rsqrt(max(deg,1))
__global__ void init_ds_kernel(int n) {
    int i = blockIdx.x * blockDim.x + threadIdx.x;
    if (i >= n) return;
    g_cursor[i] = g_rowptr[i];
    int d = g_deg[i];
    float df = (float)(d < 1 ? 1 : d);
    g_ds[i] = rsqrtf(df);
}

__global__ void fill_csr_kernel(const int* __restrict__ src,
                                const int* __restrict__ dst, int e) {
    int i = blockIdx.x * blockDim.x + threadIdx.x;
    if (i >= e) return;
    int d = dst[i];
    int pos = atomicAdd(&g_cursor[d], 1);
    g_srcs[pos] = src[i];
}

// ---------------- feature pipeline ----------------------------------------
// Xcat slice 0 = signal; y = signal * ds
__global__ void init_x_kernel(const float* __restrict__ signal, int n) {
    int idx = blockIdx.x * blockDim.x + threadIdx.x;
    if (idx >= n * NF) return;
    int node = idx >> 6;
    int f = idx & 63;
    float v = signal[idx];
    g_Xcat[(size_t)node * NFK + f] = v;
    g_y[idx] = v * g_ds[node];
}

// Gather-sum: 16 threads per node, one float4 per thread (64 feats).
__global__ void agg_kernel(int n) {
    int t = blockIdx.x * blockDim.x + threadIdx.x;
    int gid = t >> 4;           // node
    int lane = t & 15;          // float4 slot
    if (gid >= n) return;
    const float4* y4 = reinterpret_cast<const float4*>(g_y);
    int b = g_rowptr[gid];
    int e = g_rowptr[gid + 1];
    float4 acc = make_float4(0.f, 0.f, 0.f, 0.f);
    int j = b;
    for (; j + 1 < e; j += 2) {
        int s0 = g_srcs[j];
        int s1 = g_srcs[j + 1];
        float4 v0 = y4[s0 * 16 + lane];
        float4 v1 = y4[s1 * 16 + lane];
        acc.x += v0.x + v1.x;
        acc.y += v0.y + v1.y;
        acc.z += v0.z + v1.z;
        acc.w += v0.w + v1.w;
    }
    if (j < e) {
        int s0 = g_srcs[j];
        float4 v0 = y4[s0 * 16 + lane];
        acc.x += v0.x; acc.y += v0.y; acc.z += v0.z; acc.w += v0.w;
    }
    reinterpret_cast<float4*>(g_agg)[gid * 16 + lane] = acc;
}

// Chebyshev recurrence; also writes y for the next pass.
// step==1: X1 = -r*Lx + (r-1)*X0
// step>=2: Xi = -2r*Lx + 2(r-1)*X_{i-1} - X_{i-2}
__global__ void recur_kernel(const float* __restrict__ lam, int step, int n) {
    int idx = blockIdx.x * blockDim.x + threadIdx.x;
    if (idx >= n * NF) return;
    int node = idx >> 6;
    int f = idx & 63;
    float ds = g_ds[node];
    float r = 2.0f / lam[0];
    float Lx = g_agg[idx] * ds;
    size_t rowbase = (size_t)node * NFK;
    float xp = g_Xcat[rowbase + (size_t)(step - 1) * NF + f];
    float v;
    if (step == 1) {
        v = -r * Lx + (r - 1.0f) * xp;
    } else {
        float xpp = g_Xcat[rowbase + (size_t)(step - 2) * NF + f];
        v = -2.0f * r * Lx + 2.0f * (r - 1.0f) * xp - xpp;
    }
    g_Xcat[rowbase + (size_t)step * NF + f] = v;
    g_y[idx] = v * ds;
}

// ---------------- SGEMM: C = relu(Xcat @ W + b), M x 256 x 256 -------------
// 128x128 block tile, BK=8, 256 threads, 8x8 micro-tile.
__global__ __launch_bounds__(256) void sgemm_kernel(
    const float* __restrict__ B,     // W [256,256]
    const float* __restrict__ bias,  // [256]
    float* __restrict__ C, int M) {
    __shared__ float As[8][128];
    __shared__ float Bs[8][128];
    const float* A = g_Xcat;
    int tid = threadIdx.x;
    int tx = tid & 15;     // 0..15  (cols)
    int ty = tid >> 4;     // 0..15  (rows)
    int rowBase = blockIdx.x * 128;
    int colBase = blockIdx.y * 128;

    int aRow = tid >> 1;          // 0..127
    int aCol = (tid & 1) * 4;     // 0 or 4
    int bRow = tid >> 5;          // 0..7
    int bCol = (tid & 31) * 4;    // 0..124

    float acc[8][8];
#pragma unroll
    for (int i = 0; i < 8; i++)
#pragma unroll
        for (int j = 0; j < 8; j++) acc[i][j] = 0.f;

    for (int k0 = 0; k0 < 256; k0 += 8) {
        float4 av = make_float4(0.f, 0.f, 0.f, 0.f);
        int gr = rowBase + aRow;
        if (gr < M) av = *(const float4*)&A[(size_t)gr * 256 + k0 + aCol];
        As[aCol + 0][aRow] = av.x;
        As[aCol + 1][aRow] = av.y;
        As[aCol + 2][aRow] = av.z;
        As[aCol + 3][aRow] = av.w;
        float4 bv = *(const float4*)&B[(size_t)(k0 + bRow) * 256 + colBase + bCol];
        *(float4*)&Bs[bRow][bCol] = bv;
        __syncthreads();
#pragma unroll
        for (int k = 0; k < 8; k++) {
            float ra[8], rb[8];
#pragma unroll
            for (int i = 0; i < 8; i++) ra[i] = As[k][ty * 8 + i];
#pragma unroll
            for (int j = 0; j < 8; j++) rb[j] = Bs[k][tx * 8 + j];
#pragma unroll
            for (int i = 0; i < 8; i++)
#pragma unroll
                for (int j = 0; j < 8; j++) acc[i][j] += ra[i] * rb[j];
        }
        __syncthreads();
    }

#pragma unroll
    for (int i = 0; i < 8; i++) {
        int r = rowBase + ty * 8 + i;
        if (r >= M) continue;
#pragma unroll
        for (int j = 0; j < 8; j += 4) {
            int c = colBase + tx * 8 + j;
            float4 o;
            o.x = fmaxf(acc[i][j + 0] + bias[c + 0], 0.f);
            o.y = fmaxf(acc[i][j + 1] + bias[c + 1], 0.f);
            o.z = fmaxf(acc[i][j + 2] + bias[c + 2], 0.f);
            o.w = fmaxf(acc[i][j + 3] + bias[c + 3], 0.f);
            *(float4*)&C[(size_t)r * 256 + c] = o;
        }
    }
}

// ---------------- launch ---------------------------------------------------
extern "C" void kernel_launch(void* const* d_in, const int* in_sizes, int n_in,
                              void* d_out, int out_size) {
    const float* signal = (const float*)d_in[0];
    const int*   src    = (const int*)d_in[1];
    const int*   dst    = (const int*)d_in[2];
    const float* lam    = (const float*)d_in[3];
    const float* W      = (const float*)d_in[4];
    const float* bias   = (const float*)d_in[5];
    float* out = (float*)d_out;

    int n = in_sizes[0] / NF;   // 50000
    int e = in_sizes[1];        // 800000

    int nThreads = 256;
    int nBlocksN = (n + nThreads - 1) / nThreads;
    int nBlocksE = (e + nThreads - 1) / nThreads;
    int nScanBlocks = (n + 1023) / 1024;          // 49
    int nBlocksNF = (n * NF + nThreads - 1) / nThreads;
    int nBlocksAgg = (n * 16 + nThreads - 1) / nThreads;  // 16 thr/node

    zero_deg_kernel<<<nBlocksN, nThreads>>>(n);
    count_deg_kernel<<<nBlocksE, nThreads>>>(dst, e);
    scanA_kernel<<<nScanBlocks, 1024>>>(n);
    scanB_kernel<<<1, 64>>>(nScanBlocks);
    scanC_kernel<<<nScanBlocks, 1024>>>(n);
    init_ds_kernel<<<nBlocksN, nThreads>>>(n);
    fill_csr_kernel<<<nBlocksE, nThreads>>>(src, dst, e);
    init_x_kernel<<<nBlocksNF, nThreads>>>(signal, n);

    for (int step = 1; step <= 3; step++) {
        agg_kernel<<<nBlocksAgg, nThreads>>>(n);
        recur_kernel<<<nBlocksNF, nThreads>>>(lam, step, n);
    }

    dim3 gemmGrid((n + 127) / 128, 2);
    sgemm_kernel<<<gemmGrid, 256>>>(W, bias, out, n);
}

// round 14
// speedup vs baseline: 1.3330x; 1.3330x over previous
#include <cuda_runtime.h>
#include <cuda_bf16.h>
#include <cstdint>

// ChebConv K=4: N=50000, E=800000, 64 in-feats, 256 out-feats.
// R1-proven sparse pipeline (CSR build -> 3x [gather-sum -> recurrence],
// separate launches, race-free by construction) + R9-proven bf16 split GEMM
// via mma.sync.m16n8k16 (Ahi*Bhi + Ahi*Blo + Alo*Bhi, fp32 accum) + bias/ReLU.
// kernel_launch contains ONLY kernel launches (graph-capture safe).

#define NMAX 50000
#define EMAX 800000
#define NF   64
#define NFK  256

// ---------------- scratch (R1-proven footprint) -----------------------------
__device__ int   g_deg[NMAX];
__device__ int   g_rowptr[NMAX + 1];
__device__ int   g_cursor[NMAX];
__device__ int   g_blocksum[64];
__device__ int   g_srcs[EMAX];
__device__ float g_ds[NMAX];
__device__ __align__(16) float g_y[NMAX * NF];      // X_prev * d^{-1/2}
__device__ __align__(16) float g_agg[NMAX * NF];    // gather result
__device__ __align__(16) float g_Xcat[(size_t)NMAX * NFK];
// W split to bf16 hi/lo, stored transposed as [n][k] (B col-major for mma)
__device__ __align__(16) unsigned short g_Wthi[256 * 256];
__device__ __align__(16) unsigned short g_Wtlo[256 * 256];

// ---------------- helpers ---------------------------------------------------
__device__ __forceinline__ uint32_t smem_to_u32(const void* p) {
    uint32_t a;
    asm("{ .reg .u64 t; cvta.to.shared.u64 t, %1; cvt.u32.u64 %0, t; }"
        : "=r"(a) : "l"(p));
    return a;
}

__device__ __forceinline__ void split_bf16(float x, unsigned short& h, unsigned short& l) {
    __nv_bfloat16 hb = __float2bfloat16_rn(x);
    float r = x - __bfloat162float(hb);
    __nv_bfloat16 lb = __float2bfloat16_rn(r);
    h = *reinterpret_cast<unsigned short*>(&hb);
    l = *reinterpret_cast<unsigned short*>(&lb);
}

#define LDSM_X4(r0, r1, r2, r3, addr) \
    asm volatile("ldmatrix.sync.aligned.m8n8.x4.shared.b16 {%0,%1,%2,%3}, [%4];" \
        : "=r"(r0), "=r"(r1), "=r"(r2), "=r"(r3) : "r"(addr))

__device__ __forceinline__ void mma_bf16(float* c, const uint32_t* a,
                                         uint32_t b0, uint32_t b1) {
    asm volatile(
        "mma.sync.aligned.m16n8k16.row.col.f32.bf16.bf16.f32 "
        "{%0,%1,%2,%3}, {%4,%5,%6,%7}, {%8,%9}, {%0,%1,%2,%3};"
        : "+f"(c[0]), "+f"(c[1]), "+f"(c[2]), "+f"(c[3])
        : "r"(a[0]), "r"(a[1]), "r"(a[2]), "r"(a[3]), "r"(b0), "r"(b1));
}

// SW64 swizzle for 64-byte rows (conflict-free ldmatrix: per 8-row matrix the
// XOR keys {0,16,32,48} x {even,odd row segment} cover all 32 banks once).
__device__ __forceinline__ uint32_t swz64(uint32_t off) {
    return off ^ ((off >> 3) & 0x30);
}

// ---------------- CSR build (R1-proven) -------------------------------------
__global__ void zero_deg_kernel(int n) {
    int i = blockIdx.x * blockDim.x + threadIdx.x;
    if (i < n) g_deg[i] = 0;
}
__global__ void count_deg_kernel(const int* __restrict__ dst, int e) {
    int i = blockIdx.x * blockDim.x + threadIdx.x;
    if (i < e) atomicAdd(&g_deg[dst[i]], 1);
}
__global__ void scanA_kernel(int n) {
    __shared__ int sh[1024];
    int i = blockIdx.x * 1024 + threadIdx.x;
    int v = (i < n) ? g_deg[i] : 0;
    sh[threadIdx.x] = v;
    __syncthreads();
    for (int off = 1; off < 1024; off <<= 1) {
        int u = (threadIdx.x >= (unsigned)off) ? sh[threadIdx.x - off] : 0;
        __syncthreads();
        sh[threadIdx.x] += u;
        __syncthreads();
    }
    if (i < n) g_rowptr[i + 1] = sh[threadIdx.x];
    if (threadIdx.x == 1023) g_blocksum[blockIdx.x] = sh[1023];
}
__global__ void scanB_kernel(int nb) {
    __shared__ int sh[64];
    int t = threadIdx.x;
    int v = (t < nb) ? g_blocksum[t] : 0;
    sh[t] = v;
    __syncthreads();
    for (int off = 1; off < 64; off <<= 1) {
        int u = (t >= off) ? sh[t - off] : 0;
        __syncthreads();
        sh[t] += u;
        __syncthreads();
    }
    if (t < nb) g_blocksum[t] = sh[t] - v;
}
__global__ void scanC_kernel(int n) {
    int i = blockIdx.x * 1024 + threadIdx.x;
    if (i < n) {
        int v = g_rowptr[i + 1] + g_blocksum[blockIdx.x];
        g_rowptr[i + 1] = v;
        int d = g_deg[i];
        g_cursor[i] = v - d;
        g_ds[i] = rsqrtf((float)(d < 1 ? 1 : d));
    }
    if (i == 0) g_rowptr[0] = 0;
}
__global__ void fill_csr_kernel(const int* __restrict__ src,
                                const int* __restrict__ dst, int e) {
    int i = blockIdx.x * blockDim.x + threadIdx.x;
    if (i >= e) return;
    int d = dst[i];
    int pos = atomicAdd(&g_cursor[d], 1);
    g_srcs[pos] = src[i];
}

// ---------------- feature pipeline (R1-proven structure) --------------------
__global__ void init_x_kernel(const float* __restrict__ signal, int n) {
    int idx = blockIdx.x * blockDim.x + threadIdx.x;
    if (idx >= n * NF) return;
    int node = idx >> 6;
    int f = idx & 63;
    float v = signal[idx];
    g_Xcat[(size_t)node * NFK + f] = v;
    g_y[idx] = v * g_ds[node];
}

// Gather-sum: 16 threads per node, one float4 per thread (64 feats).
// Reads g_y, writes g_agg — separate launch from the y update (race-free).
__global__ void agg_kernel(int n) {
    int t = blockIdx.x * blockDim.x + threadIdx.x;
    int gid = t >> 4;
    int lane = t & 15;
    if (gid >= n) return;
    const float4* y4 = reinterpret_cast<const float4*>(g_y);
    int b = g_rowptr[gid];
    int e = g_rowptr[gid + 1];
    float4 acc = make_float4(0.f, 0.f, 0.f, 0.f);
    int j = b;
    for (; j + 1 < e; j += 2) {
        int s0 = g_srcs[j];
        int s1 = g_srcs[j + 1];
        float4 v0 = y4[s0 * 16 + lane];
        float4 v1 = y4[s1 * 16 + lane];
        acc.x += v0.x + v1.x;
        acc.y += v0.y + v1.y;
        acc.z += v0.z + v1.z;
        acc.w += v0.w + v1.w;
    }
    if (j < e) {
        int s0 = g_srcs[j];
        float4 v0 = y4[s0 * 16 + lane];
        acc.x += v0.x; acc.y += v0.y; acc.z += v0.z; acc.w += v0.w;
    }
    reinterpret_cast<float4*>(g_agg)[gid * 16 + lane] = acc;
}

// Chebyshev recurrence; also writes y for the next pass. (R1-proven)
__global__ void recur_kernel(const float* __restrict__ lam, int step, int n) {
    int idx = blockIdx.x * blockDim.x + threadIdx.x;
    if (idx >= n * NF) return;
    int node = idx >> 6;
    int f = idx & 63;
    float ds = g_ds[node];
    float r = 2.0f / lam[0];
    float Lx = g_agg[idx] * ds;
    size_t rowbase = (size_t)node * NFK;
    float xp = g_Xcat[rowbase + (size_t)(step - 1) * NF + f];
    float v;
    if (step == 1) {
        v = -r * Lx + (r - 1.0f) * xp;
    } else {
        float xpp = g_Xcat[rowbase + (size_t)(step - 2) * NF + f];
        v = -2.0f * r * Lx + 2.0f * (r - 1.0f) * xp - xpp;
    }
    g_Xcat[rowbase + (size_t)step * NF + f] = v;
    g_y[idx] = v * ds;
}

// ---------------- W -> bf16 hi/lo, transposed [n][k] ------------------------
__global__ void convert_w_kernel(const float* __restrict__ W) {
    int id = blockIdx.x * blockDim.x + threadIdx.x;  // 0..16383
    if (id >= 256 * 64) return;
    int kk = id >> 6;         // 0..255
    int n4 = (id & 63) << 2;  // 0..252
    float4 w = *reinterpret_cast<const float4*>(&W[(size_t)kk * 256 + n4]);
    unsigned short h, l;
    split_bf16(w.x, h, l);
    g_Wthi[(n4 + 0) * 256 + kk] = h; g_Wtlo[(n4 + 0) * 256 + kk] = l;
    split_bf16(w.y, h, l);
    g_Wthi[(n4 + 1) * 256 + kk] = h; g_Wtlo[(n4 + 1) * 256 + kk] = l;
    split_bf16(w.z, h, l);
    g_Wthi[(n4 + 2) * 256 + kk] = h; g_Wtlo[(n4 + 2) * 256 + kk] = l;
    split_bf16(w.w, h, l);
    g_Wthi[(n4 + 3) * 256 + kk] = h; g_Wtlo[(n4 + 3) * 256 + kk] = l;
}

// ---------------- GEMM: out = relu(Xcat @ W + b) (R9-proven to execute) -----
// CTA tile 128x128; 8 warps (2m x 4n), warp tile 64x32; K in 8 chunks of 32.
// STATIC smem (32KB): Ahi/Alo/Bhi/Blo, each 128 rows x 32 bf16 = 8KB,
// 64B rows with SW64 XOR swizzle (conflict-free ldmatrix).
__global__ __launch_bounds__(256, 2) void gemm_mma_kernel(
    const float* __restrict__ bias, float* __restrict__ out, int M) {
    __shared__ __align__(16) unsigned char smAhi[8192];
    __shared__ __align__(16) unsigned char smAlo[8192];
    __shared__ __align__(16) unsigned char smBhi[8192];
    __shared__ __align__(16) unsigned char smBlo[8192];
    uint32_t sAhi = smem_to_u32(smAhi);
    uint32_t sAlo = smem_to_u32(smAlo);
    uint32_t sBhi = smem_to_u32(smBhi);
    uint32_t sBlo = smem_to_u32(smBlo);

    int tid = threadIdx.x;
    int wid = tid >> 5;
    int lane = tid & 31;
    int warpM = wid >> 2;      // 0..1
    int warpN = wid & 3;       // 0..3
    int rowBase = blockIdx.x * 128;
    int colBase = blockIdx.y * 128;

    // loader mapping: row = tid>>1 (0..127), half = (tid&1)*16 elements
    int ldRow = tid >> 1;
    int ldK = (tid & 1) * 16;
    bool avalid = (rowBase + ldRow) < M;

    float acc[4][4][4];
#pragma unroll
    for (int i = 0; i < 4; i++)
#pragma unroll
        for (int j = 0; j < 4; j++)
#pragma unroll
            for (int q = 0; q < 4; q++) acc[i][j][q] = 0.f;

    int laneRow = lane & 15;
    uint32_t laneK = (uint32_t)(lane & 16);  // +0 or +16 bytes

    for (int ck = 0; ck < 8; ck++) {
        // ---- A chunk: fp32 -> bf16 hi/lo into SW64-swizzled smem ----
        {
            const float* Ap = g_Xcat + (size_t)(rowBase + ldRow) * 256 + ck * 32 + ldK;
#pragma unroll
            for (int i = 0; i < 4; i++) {
                float4 v = avalid ? *reinterpret_cast<const float4*>(Ap + i * 4)
                                  : make_float4(0.f, 0.f, 0.f, 0.f);
                unsigned short h0, h1, h2, h3, l0, l1, l2, l3;
                split_bf16(v.x, h0, l0);
                split_bf16(v.y, h1, l1);
                split_bf16(v.z, h2, l2);
                split_bf16(v.w, h3, l3);
                uint32_t off = (uint32_t)(ldRow * 64 + (ldK + i * 4) * 2);  // 8B-aligned
                uint32_t s = swz64(off);
                uint2 ph, pl;
                ph.x = (uint32_t)h0 | ((uint32_t)h1 << 16);
                ph.y = (uint32_t)h2 | ((uint32_t)h3 << 16);
                pl.x = (uint32_t)l0 | ((uint32_t)l1 << 16);
                pl.y = (uint32_t)l2 | ((uint32_t)l3 << 16);
                *reinterpret_cast<uint2*>(smAhi + s) = ph;
                *reinterpret_cast<uint2*>(smAlo + s) = pl;
            }
        }
        // ---- B chunk: bf16 [n][k] copy into SW64-swizzled smem ----
        {
            const unsigned short* Bh = g_Wthi + (size_t)(colBase + ldRow) * 256 + ck * 32 + ldK;
            const unsigned short* Bl = g_Wtlo + (size_t)(colBase + ldRow) * 256 + ck * 32 + ldK;
#pragma unroll
            for (int i = 0; i < 2; i++) {  // 2 x 16B = 16 bf16
                uint4 vh = *reinterpret_cast<const uint4*>(Bh + i * 8);
                uint4 vl = *reinterpret_cast<const uint4*>(Bl + i * 8);
                uint32_t off = (uint32_t)(ldRow * 64 + (ldK + i * 8) * 2);  // 16B-aligned
                uint32_t s = swz64(off);
                *reinterpret_cast<uint4*>(smBhi + s) = vh;
                *reinterpret_cast<uint4*>(smBlo + s) = vl;
            }
        }
        __syncthreads();

#pragma unroll
        for (int combo = 0; combo < 3; combo++) {
            uint32_t aBase = (combo == 2) ? sAlo : sAhi;
            uint32_t bBase = (combo == 1) ? sBlo : sBhi;
#pragma unroll
            for (int ks = 0; ks < 2; ks++) {
                uint32_t kOff = (uint32_t)(ks * 32) + laneK;
                uint32_t a[4][4];
#pragma unroll
                for (int mt = 0; mt < 4; mt++) {
                    uint32_t off = (uint32_t)((warpM * 64 + mt * 16 + laneRow) * 64) + kOff;
                    LDSM_X4(a[mt][0], a[mt][1], a[mt][2], a[mt][3], aBase + swz64(off));
                }
                uint32_t b[2][4];
#pragma unroll
                for (int nt = 0; nt < 2; nt++) {
                    uint32_t off = (uint32_t)((warpN * 32 + nt * 16 + laneRow) * 64) + kOff;
                    LDSM_X4(b[nt][0], b[nt][1], b[nt][2], b[nt][3], bBase + swz64(off));
                }
#pragma unroll
                for (int mt = 0; mt < 4; mt++)
#pragma unroll
                    for (int j = 0; j < 4; j++) {
                        int nt = j >> 1;
                        int sub = j & 1;
                        mma_bf16(acc[mt][j], a[mt], b[nt][sub], b[nt][2 + sub]);
                    }
            }
        }
        __syncthreads();
    }

    // ---- epilogue: bias + relu, direct global stores ----
    int m0g = rowBase + warpM * 64;
    int n0g = colBase + warpN * 32;
    int rOff = lane >> 2;
    int cOff = (lane & 3) * 2;
#pragma unroll
    for (int j = 0; j < 4; j++) {
        int col = n0g + j * 8 + cOff;
        float b0 = bias[col];
        float b1 = bias[col + 1];
#pragma unroll
        for (int mt = 0; mt < 4; mt++) {
            int row0 = m0g + mt * 16 + rOff;
            if (row0 < M) {
                float2 o;
                o.x = fmaxf(acc[mt][j][0] + b0, 0.f);
                o.y = fmaxf(acc[mt][j][1] + b1, 0.f);
                *reinterpret_cast<float2*>(&out[(size_t)row0 * 256 + col]) = o;
            }
            int row1 = row0 + 8;
            if (row1 < M) {
                float2 o;
                o.x = fmaxf(acc[mt][j][2] + b0, 0.f);
                o.y = fmaxf(acc[mt][j][3] + b1, 0.f);
                *reinterpret_cast<float2*>(&out[(size_t)row1 * 256 + col]) = o;
            }
        }
    }
}

// ---------------- launch (ONLY kernel launches — graph-capture safe) --------
extern "C" void kernel_launch(void* const* d_in, const int* in_sizes, int n_in,
                              void* d_out, int out_size) {
    const float* signal = (const float*)d_in[0];
    const int*   src    = (const int*)d_in[1];
    const int*   dst    = (const int*)d_in[2];
    const float* lam    = (const float*)d_in[3];
    const float* W      = (const float*)d_in[4];
    const float* bias   = (const float*)d_in[5];
    float* out = (float*)d_out;

    int n = in_sizes[0] / NF;   // 50000
    int e = in_sizes[1];        // 800000

    int nThreads = 256;
    int nBlocksN = (n + nThreads - 1) / nThreads;
    int nBlocksE = (e + nThreads - 1) / nThreads;
    int nScanBlocks = (n + 1023) / 1024;
    int nBlocksNF = (n * NF + nThreads - 1) / nThreads;
    int nBlocksAgg = (n * 16 + nThreads - 1) / nThreads;

    zero_deg_kernel<<<nBlocksN, nThreads>>>(n);
    count_deg_kernel<<<nBlocksE, nThreads>>>(dst, e);
    scanA_kernel<<<nScanBlocks, 1024>>>(n);
    scanB_kernel<<<1, 64>>>(nScanBlocks);
    scanC_kernel<<<nScanBlocks, 1024>>>(n);
    fill_csr_kernel<<<nBlocksE, nThreads>>>(src, dst, e);
    init_x_kernel<<<nBlocksNF, nThreads>>>(signal, n);
    convert_w_kernel<<<64, 256>>>(W);

    for (int step = 1; step <= 3; step++) {
        agg_kernel<<<nBlocksAgg, nThreads>>>(n);
        recur_kernel<<<nBlocksNF, nThreads>>>(lam, step, n);
    }

    dim3 gemmGrid((n + 127) / 128, 2);  // (391, 2)
    gemm_mma_kernel<<<gemmGrid, 256>>>(bias, out, n);
}

// round 16
// speedup vs baseline: 1.4247x; 1.0688x over previous
#include <cuda_runtime.h>
#include <cuda_bf16.h>
#include <cstdint>

// ChebConv K=4: N=50000, E=800000, 64 in-feats, 256 out-feats.
// R14-proven pipeline with: single-kernel decoupled-lookback scan (replaces
// scanA/B/C), convert_w merged into init_x, and cp.async B-tile loads in the
// bf16 split GEMM (mma.sync.m16n8k16, Ahi*Bhi + Ahi*Blo + Alo*Bhi).
// kernel_launch contains ONLY kernel launches (graph-capture safe).

#define NMAX 50000
#define EMAX 800000
#define NF   64
#define NFK  256

// ---------------- scratch ---------------------------------------------------
__device__ int   g_deg[NMAX];
__device__ int   g_rowptr[NMAX + 1];
__device__ int   g_cursor[NMAX];
__device__ int   g_srcs[EMAX];
__device__ float g_ds[NMAX];
// decoupled-lookback scan state (49 blocks used; zeroed by zero_deg each call)
__device__ volatile int g_scan_agg[64];
__device__ volatile int g_scan_pref[64];
__device__ volatile int g_scan_flag[64];   // 0=invalid, 1=agg ready, 2=prefix ready
__device__ __align__(16) float g_y[NMAX * NF];      // X_prev * d^{-1/2}
__device__ __align__(16) float g_agg[NMAX * NF];    // gather result
__device__ __align__(16) float g_Xcat[(size_t)NMAX * NFK];
// W split to bf16 hi/lo, stored transposed as [n][k] (B col-major for mma)
__device__ __align__(16) unsigned short g_Wthi[256 * 256];
__device__ __align__(16) unsigned short g_Wtlo[256 * 256];

// ---------------- helpers ---------------------------------------------------
__device__ __forceinline__ uint32_t smem_to_u32(const void* p) {
    uint32_t a;
    asm("{ .reg .u64 t; cvta.to.shared.u64 t, %1; cvt.u32.u64 %0, t; }"
        : "=r"(a) : "l"(p));
    return a;
}

__device__ __forceinline__ void split_bf16(float x, unsigned short& h, unsigned short& l) {
    __nv_bfloat16 hb = __float2bfloat16_rn(x);
    float r = x - __bfloat162float(hb);
    __nv_bfloat16 lb = __float2bfloat16_rn(r);
    h = *reinterpret_cast<unsigned short*>(&hb);
    l = *reinterpret_cast<unsigned short*>(&lb);
}

#define LDSM_X4(r0, r1, r2, r3, addr) \
    asm volatile("ldmatrix.sync.aligned.m8n8.x4.shared.b16 {%0,%1,%2,%3}, [%4];" \
        : "=r"(r0), "=r"(r1), "=r"(r2), "=r"(r3) : "r"(addr))

#define CP_ASYNC16(dst_smem, src_gmem) \
    asm volatile("cp.async.cg.shared.global [%0], [%1], 16;" \
        :: "r"(dst_smem), "l"(src_gmem) : "memory")
#define CP_ASYNC_COMMIT_WAIT() \
    asm volatile("cp.async.commit_group;\n\tcp.async.wait_group 0;" ::: "memory")

__device__ __forceinline__ void mma_bf16(float* c, const uint32_t* a,
                                         uint32_t b0, uint32_t b1) {
    asm volatile(
        "mma.sync.aligned.m16n8k16.row.col.f32.bf16.bf16.f32 "
        "{%0,%1,%2,%3}, {%4,%5,%6,%7}, {%8,%9}, {%0,%1,%2,%3};"
        : "+f"(c[0]), "+f"(c[1]), "+f"(c[2]), "+f"(c[3])
        : "r"(a[0]), "r"(a[1]), "r"(a[2]), "r"(a[3]), "r"(b0), "r"(b1));
}

// SW64 swizzle for 64-byte rows (conflict-free ldmatrix)
__device__ __forceinline__ uint32_t swz64(uint32_t off) {
    return off ^ ((off >> 3) & 0x30);
}

// ---------------- CSR build ------------------------------------------------
__global__ void zero_deg_kernel(int n) {
    int i = blockIdx.x * blockDim.x + threadIdx.x;
    if (i < n) g_deg[i] = 0;
    if (blockIdx.x == 0 && threadIdx.x < 64) {
        g_scan_flag[threadIdx.x] = 0;
        g_scan_agg[threadIdx.x] = 0;
        g_scan_pref[threadIdx.x] = 0;
    }
}
__global__ void count_deg_kernel(const int* __restrict__ dst, int e) {
    int i = blockIdx.x * blockDim.x + threadIdx.x;
    if (i < e) atomicAdd(&g_deg[dst[i]], 1);
}

// Single-kernel scan (decoupled lookback) + cursor + ds init.
// grid = ceil(n/1024) = 49 blocks (all co-resident), block = 1024.
__global__ void scan_kernel(int n) {
    __shared__ int sh[1024];
    __shared__ int s_excl;
    int b = blockIdx.x;
    int i = b * 1024 + threadIdx.x;
    int v = (i < n) ? g_deg[i] : 0;
    sh[threadIdx.x] = v;
    __syncthreads();
    for (int off = 1; off < 1024; off <<= 1) {
        int u = (threadIdx.x >= (unsigned)off) ? sh[threadIdx.x - off] : 0;
        __syncthreads();
        sh[threadIdx.x] += u;
        __syncthreads();
    }
    int incl = sh[threadIdx.x];
    int total = sh[1023];

    if (threadIdx.x == 0) {
        if (b == 0) {
            g_scan_pref[0] = total;
            __threadfence();
            g_scan_flag[0] = 2;
            s_excl = 0;
        } else {
            g_scan_agg[b] = total;
            __threadfence();
            g_scan_flag[b] = 1;
        }
    }
    if (b > 0 && threadIdx.x < 32) {
        int lane = threadIdx.x;
        int sum = 0;
        int j = b - 1;
        while (true) {
            int idx = j - lane;
            int f = 0, vv = 0;
            if (idx >= 0) {
                do { f = g_scan_flag[idx]; } while (f == 0);
                vv = (f == 2) ? g_scan_pref[idx] : g_scan_agg[idx];
            }
            unsigned pm = __ballot_sync(0xffffffffu, idx >= 0 && f == 2);
            if (pm) {
                int fp = __ffs(pm) - 1;  // closest predecessor with full prefix
                int contrib = (lane <= fp) ? vv : 0;
                for (int o = 16; o; o >>= 1) contrib += __shfl_xor_sync(0xffffffffu, contrib, o);
                sum += contrib;
                break;
            } else {
                int contrib = (idx >= 0) ? vv : 0;
                for (int o = 16; o; o >>= 1) contrib += __shfl_xor_sync(0xffffffffu, contrib, o);
                sum += contrib;
                j -= 32;
                if (j < 0) break;  // unreachable (block 0 publishes a prefix)
            }
        }
        if (lane == 0) {
            g_scan_pref[b] = sum + total;
            __threadfence();
            g_scan_flag[b] = 2;
            s_excl = sum;
        }
    }
    __syncthreads();
    int excl = s_excl;
    if (i < n) {
        int r = incl + excl;
        g_rowptr[i + 1] = r;
        int d = g_deg[i];
        g_cursor[i] = r - d;
        g_ds[i] = rsqrtf((float)(d < 1 ? 1 : d));
    }
    if (i == 0) g_rowptr[0] = 0;
}

__global__ void fill_csr_kernel(const int* __restrict__ src,
                                const int* __restrict__ dst, int e) {
    int i = blockIdx.x * blockDim.x + threadIdx.x;
    if (i >= e) return;
    int d = dst[i];
    int pos = atomicAdd(&g_cursor[d], 1);
    g_srcs[pos] = src[i];
}

// ---------------- init X (+ fold in W conversion: one launch) ---------------
// blocks [0, nBlocksX): init_x role; blocks [nBlocksX, nBlocksX+64): convert_w.
__global__ void init_xw_kernel(const float* __restrict__ signal,
                               const float* __restrict__ W,
                               int n, int nBlocksX) {
    if (blockIdx.x >= (unsigned)nBlocksX) {
        int id = (blockIdx.x - nBlocksX) * 256 + threadIdx.x;  // 0..16383
        if (id >= 256 * 64) return;
        int kk = id >> 6;         // 0..255
        int n4 = (id & 63) << 2;  // 0..252
        float4 w = *reinterpret_cast<const float4*>(&W[(size_t)kk * 256 + n4]);
        unsigned short h, l;
        split_bf16(w.x, h, l);
        g_Wthi[(n4 + 0) * 256 + kk] = h; g_Wtlo[(n4 + 0) * 256 + kk] = l;
        split_bf16(w.y, h, l);
        g_Wthi[(n4 + 1) * 256 + kk] = h; g_Wtlo[(n4 + 1) * 256 + kk] = l;
        split_bf16(w.z, h, l);
        g_Wthi[(n4 + 2) * 256 + kk] = h; g_Wtlo[(n4 + 2) * 256 + kk] = l;
        split_bf16(w.w, h, l);
        g_Wthi[(n4 + 3) * 256 + kk] = h; g_Wtlo[(n4 + 3) * 256 + kk] = l;
        return;
    }
    int idx = blockIdx.x * 256 + threadIdx.x;
    if (idx >= n * NF) return;
    int node = idx >> 6;
    int f = idx & 63;
    float v = signal[idx];
    g_Xcat[(size_t)node * NFK + f] = v;
    g_y[idx] = v * g_ds[node];
}

// ---------------- gather-sum (R14-proven) -----------------------------------
__global__ void agg_kernel(int n) {
    int t = blockIdx.x * blockDim.x + threadIdx.x;
    int gid = t >> 4;
    int lane = t & 15;
    if (gid >= n) return;
    const float4* y4 = reinterpret_cast<const float4*>(g_y);
    int b = g_rowptr[gid];
    int e = g_rowptr[gid + 1];
    float4 acc = make_float4(0.f, 0.f, 0.f, 0.f);
    int j = b;
    for (; j + 1 < e; j += 2) {
        int s0 = g_srcs[j];
        int s1 = g_srcs[j + 1];
        float4 v0 = y4[s0 * 16 + lane];
        float4 v1 = y4[s1 * 16 + lane];
        acc.x += v0.x + v1.x;
        acc.y += v0.y + v1.y;
        acc.z += v0.z + v1.z;
        acc.w += v0.w + v1.w;
    }
    if (j < e) {
        int s0 = g_srcs[j];
        float4 v0 = y4[s0 * 16 + lane];
        acc.x += v0.x; acc.y += v0.y; acc.z += v0.z; acc.w += v0.w;
    }
    reinterpret_cast<float4*>(g_agg)[gid * 16 + lane] = acc;
}

// ---------------- Chebyshev recurrence (R14-proven) -------------------------
__global__ void recur_kernel(const float* __restrict__ lam, int step, int n) {
    int idx = blockIdx.x * blockDim.x + threadIdx.x;
    if (idx >= n * NF) return;
    int node = idx >> 6;
    int f = idx & 63;
    float ds = g_ds[node];
    float r = 2.0f / lam[0];
    float Lx = g_agg[idx] * ds;
    size_t rowbase = (size_t)node * NFK;
    float xp = g_Xcat[rowbase + (size_t)(step - 1) * NF + f];
    float v;
    if (step == 1) {
        v = -r * Lx + (r - 1.0f) * xp;
    } else {
        float xpp = g_Xcat[rowbase + (size_t)(step - 2) * NF + f];
        v = -2.0f * r * Lx + 2.0f * (r - 1.0f) * xp - xpp;
    }
    g_Xcat[rowbase + (size_t)step * NF + f] = v;
    g_y[idx] = v * ds;
}

// ---------------- GEMM: out = relu(Xcat @ W + b) ----------------------------
// CTA tile 128x128; 8 warps (2m x 4n), warp tile 64x32; K in 8 chunks of 32.
// STATIC smem (32KB). B tiles via cp.async (issued before A convert work).
__global__ __launch_bounds__(256, 2) void gemm_mma_kernel(
    const float* __restrict__ bias, float* __restrict__ out, int M) {
    __shared__ __align__(16) unsigned char smAhi[8192];
    __shared__ __align__(16) unsigned char smAlo[8192];
    __shared__ __align__(16) unsigned char smBhi[8192];
    __shared__ __align__(16) unsigned char smBlo[8192];
    uint32_t sAhi = smem_to_u32(smAhi);
    uint32_t sAlo = smem_to_u32(smAlo);
    uint32_t sBhi = smem_to_u32(smBhi);
    uint32_t sBlo = smem_to_u32(smBlo);

    int tid = threadIdx.x;
    int wid = tid >> 5;
    int lane = tid & 31;
    int warpM = wid >> 2;      // 0..1
    int warpN = wid & 3;       // 0..3
    int rowBase = blockIdx.x * 128;
    int colBase = blockIdx.y * 128;

    int ldRow = tid >> 1;
    int ldK = (tid & 1) * 16;
    bool avalid = (rowBase + ldRow) < M;

    float acc[4][4][4];
#pragma unroll
    for (int i = 0; i < 4; i++)
#pragma unroll
        for (int j = 0; j < 4; j++)
#pragma unroll
            for (int q = 0; q < 4; q++) acc[i][j][q] = 0.f;

    int laneRow = lane & 15;
    uint32_t laneK = (uint32_t)(lane & 16);  // +0 or +16 bytes

    for (int ck = 0; ck < 8; ck++) {
        // ---- B chunk first via cp.async (latency hides under A convert) ----
        {
            const unsigned short* Bh = g_Wthi + (size_t)(colBase + ldRow) * 256 + ck * 32 + ldK;
            const unsigned short* Bl = g_Wtlo + (size_t)(colBase + ldRow) * 256 + ck * 32 + ldK;
#pragma unroll
            for (int i = 0; i < 2; i++) {
                uint32_t off = (uint32_t)(ldRow * 64 + (ldK + i * 8) * 2);
                uint32_t s = swz64(off);
                CP_ASYNC16(sBhi + s, (const void*)(Bh + i * 8));
                CP_ASYNC16(sBlo + s, (const void*)(Bl + i * 8));
            }
        }
        // ---- A chunk: fp32 -> bf16 hi/lo into SW64-swizzled smem ----
        {
            const float* Ap = g_Xcat + (size_t)(rowBase + ldRow) * 256 + ck * 32 + ldK;
#pragma unroll
            for (int i = 0; i < 4; i++) {
                float4 v = avalid ? *reinterpret_cast<const float4*>(Ap + i * 4)
                                  : make_float4(0.f, 0.f, 0.f, 0.f);
                unsigned short h0, h1, h2, h3, l0, l1, l2, l3;
                split_bf16(v.x, h0, l0);
                split_bf16(v.y, h1, l1);
                split_bf16(v.z, h2, l2);
                split_bf16(v.w, h3, l3);
                uint32_t off = (uint32_t)(ldRow * 64 + (ldK + i * 4) * 2);
                uint32_t s = swz64(off);
                uint2 ph, pl;
                ph.x = (uint32_t)h0 | ((uint32_t)h1 << 16);
                ph.y = (uint32_t)h2 | ((uint32_t)h3 << 16);
                pl.x = (uint32_t)l0 | ((uint32_t)l1 << 16);
                pl.y = (uint32_t)l2 | ((uint32_t)l3 << 16);
                *reinterpret_cast<uint2*>(smAhi + s) = ph;
                *reinterpret_cast<uint2*>(smAlo + s) = pl;
            }
        }
        CP_ASYNC_COMMIT_WAIT();
        __syncthreads();

#pragma unroll
        for (int combo = 0; combo < 3; combo++) {
            uint32_t aBase = (combo == 2) ? sAlo : sAhi;
            uint32_t bBase = (combo == 1) ? sBlo : sBhi;
#pragma unroll
            for (int ks = 0; ks < 2; ks++) {
                uint32_t kOff = (uint32_t)(ks * 32) + laneK;
                uint32_t a[4][4];
#pragma unroll
                for (int mt = 0; mt < 4; mt++) {
                    uint32_t off = (uint32_t)((warpM * 64 + mt * 16 + laneRow) * 64) + kOff;
                    LDSM_X4(a[mt][0], a[mt][1], a[mt][2], a[mt][3], aBase + swz64(off));
                }
                uint32_t b[2][4];
#pragma unroll
                for (int nt = 0; nt < 2; nt++) {
                    uint32_t off = (uint32_t)((warpN * 32 + nt * 16 + laneRow) * 64) + kOff;
                    LDSM_X4(b[nt][0], b[nt][1], b[nt][2], b[nt][3], bBase + swz64(off));
                }
#pragma unroll
                for (int mt = 0; mt < 4; mt++)
#pragma unroll
                    for (int j = 0; j < 4; j++) {
                        int nt = j >> 1;
                        int sub = j & 1;
                        mma_bf16(acc[mt][j], a[mt], b[nt][sub], b[nt][2 + sub]);
                    }
            }
        }
        __syncthreads();
    }

    // ---- epilogue: bias + relu, direct global stores ----
    int m0g = rowBase + warpM * 64;
    int n0g = colBase + warpN * 32;
    int rOff = lane >> 2;
    int cOff = (lane & 3) * 2;
#pragma unroll
    for (int j = 0; j < 4; j++) {
        int col = n0g + j * 8 + cOff;
        float b0 = bias[col];
        float b1 = bias[col + 1];
#pragma unroll
        for (int mt = 0; mt < 4; mt++) {
            int row0 = m0g + mt * 16 + rOff;
            if (row0 < M) {
                float2 o;
                o.x = fmaxf(acc[mt][j][0] + b0, 0.f);
                o.y = fmaxf(acc[mt][j][1] + b1, 0.f);
                *reinterpret_cast<float2*>(&out[(size_t)row0 * 256 + col]) = o;
            }
            int row1 = row0 + 8;
            if (row1 < M) {
                float2 o;
                o.x = fmaxf(acc[mt][j][2] + b0, 0.f);
                o.y = fmaxf(acc[mt][j][3] + b1, 0.f);
                *reinterpret_cast<float2*>(&out[(size_t)row1 * 256 + col]) = o;
            }
        }
    }
}

// ---------------- launch (ONLY kernel launches — graph-capture safe) --------
extern "C" void kernel_launch(void* const* d_in, const int* in_sizes, int n_in,
                              void* d_out, int out_size) {
    const float* signal = (const float*)d_in[0];
    const int*   src    = (const int*)d_in[1];
    const int*   dst    = (const int*)d_in[2];
    const float* lam    = (const float*)d_in[3];
    const float* W      = (const float*)d_in[4];
    const float* bias   = (const float*)d_in[5];
    float* out = (float*)d_out;

    int n = in_sizes[0] / NF;   // 50000
    int e = in_sizes[1];        // 800000

    int nThreads = 256;
    int nBlocksN = (n + nThreads - 1) / nThreads;
    int nBlocksE = (e + nThreads - 1) / nThreads;
    int nScanBlocks = (n + 1023) / 1024;          // 49
    int nBlocksNF = (n * NF + nThreads - 1) / nThreads;
    int nBlocksAgg = (n * 16 + nThreads - 1) / nThreads;

    zero_deg_kernel<<<nBlocksN, nThreads>>>(n);
    count_deg_kernel<<<nBlocksE, nThreads>>>(dst, e);
    scan_kernel<<<nScanBlocks, 1024>>>(n);
    fill_csr_kernel<<<nBlocksE, nThreads>>>(src, dst, e);
    init_xw_kernel<<<nBlocksNF + 64, nThreads>>>(signal, W, n, nBlocksNF);

    for (int step = 1; step <= 3; step++) {
        agg_kernel<<<nBlocksAgg, nThreads>>>(n);
        recur_kernel<<<nBlocksNF, nThreads>>>(lam, step, n);
    }

    dim3 gemmGrid((n + 127) / 128, 2);  // (391, 2)
    gemm_mma_kernel<<<gemmGrid, 256>>>(bias, out, n);
}